// round 6
// baseline (speedup 1.0000x reference)
#include <cuda_runtime.h>
#include <math_constants.h>

// SMPL nearest-neighbor skinning — split-table 2-kernel pipeline.
// Kernel A (scan): CTA pair (chunk c, half h) scans half the vertex table
//   (55KB smem -> 2 CTAs/SM -> 22 warps/SM) for 704 points, packed-f32x2,
//   branchless group argmin; writes (best, bidx) to device scratch.
// Kernel B (finish): per point pick winner across halves (strict <, half0
//   wins ties == sequential first-index argmin), blend bones, epilogue.
// Output layout: [0,3n) x_bar | [3n,12n) rotation_bar | [12n,28n) T_fwd
//
// d2 rounding matches reference bit-exactly per lane:
//   dot = fma(pz,vz, fma(py,vy, mul(px,vx)));  d2 = add(fma(-2,dot,sx), |v|^2)

typedef unsigned long long ull;

__device__ __forceinline__ ull f2_mul(ull a, ull b) {
    ull r; asm("mul.rn.f32x2 %0,%1,%2;" : "=l"(r) : "l"(a), "l"(b)); return r;
}
__device__ __forceinline__ ull f2_fma(ull a, ull b, ull c) {
    ull r; asm("fma.rn.f32x2 %0,%1,%2,%3;" : "=l"(r) : "l"(a), "l"(b), "l"(c)); return r;
}
__device__ __forceinline__ ull f2_add(ull a, ull b) {
    ull r; asm("add.rn.f32x2 %0,%1,%2;" : "=l"(r) : "l"(a), "l"(b)); return r;
}
__device__ __forceinline__ ull f2_pack(float lo, float hi) {
    ull r; asm("mov.b64 %0,{%1,%2};" : "=l"(r) : "f"(lo), "f"(hi)); return r;
}
__device__ __forceinline__ float2 f2_unpack(ull v) {
    float lo, hi; asm("mov.b64 {%0,%1},%2;" : "=f"(lo), "=f"(hi) : "l"(v));
    return make_float2(lo, hi);
}

static constexpr int NPAD     = 6896;     // verts padded to multiple of 16
static constexpr int NPAIRS_H = 1724;     // pairs per half  (3448 verts)
static constexpr int NGROUPS_H = 431;     // groups of 8 per half
static constexpr int THREADS  = 352;      // 11 warps/CTA; 2 CTAs/SM
static constexpr int PTS_PER_CTA = 2 * THREADS;   // 704
static constexpr int MAXN = 100000;

// Device scratch (no allocation allowed): per-half candidates.
__device__ float g_best[2][MAXN];
__device__ int   g_bidx[2][MAXN];

// Compute the 8 d2 values of one group (exact reference rounding).
__device__ __forceinline__ void group_d2(
    const ulonglong2* __restrict__ q, ull Px, ull Py, ull Pz, ull Sx, ull M2,
    float2* a /*4 entries*/)
{
    #pragma unroll
    for (int u = 0; u < 4; ++u) {
        ulonglong2 ab = q[2 * u];                 // (vx2, vy2)
        ulonglong2 cd = q[2 * u + 1];             // (vz2, w2)
        ull dot = f2_mul(Px, ab.x);
        dot = f2_fma(Py, ab.y, dot);
        dot = f2_fma(Pz, cd.x, dot);
        a[u] = f2_unpack(f2_add(f2_fma(M2, dot, Sx), cd.y));
    }
}

// ───────────────────────── Kernel A: scan ─────────────────────────
__global__ void __launch_bounds__(THREADS, 2) scan_kernel(
    const float* __restrict__ xyz,
    const float* __restrict__ verts,
    int n, int nv)
{
    extern __shared__ float smem[];
    float4* sv4 = reinterpret_cast<float4*>(smem);   // NPAIRS_H pair-packed entries

    const int half  = blockIdx.x & 1;
    const int chunk = blockIdx.x >> 1;
    const int tid   = threadIdx.x;
    const int vbase = half * (2 * NPAIRS_H);         // first global vert of this half

    // Load this half's pair-packed table:
    //   sv4[2p]   = (vx0, vx1, vy0, vy1)
    //   sv4[2p+1] = (vz0, vz1, w0,  w1)   w = |v|^2 (mul/add rounding)
    for (int p = tid; p < NPAIRS_H; p += THREADS) {
        int j0 = vbase + 2 * p, j1 = vbase + 2 * p + 1;
        float x0 = 0.f, y0 = 0.f, z0 = 0.f, w0 = CUDART_INF_F;
        float x1 = 0.f, y1 = 0.f, z1 = 0.f, w1 = CUDART_INF_F;
        if (j0 < nv) {
            x0 = verts[3 * j0 + 0]; y0 = verts[3 * j0 + 1]; z0 = verts[3 * j0 + 2];
            w0 = __fadd_rn(__fadd_rn(__fmul_rn(x0, x0), __fmul_rn(y0, y0)),
                           __fmul_rn(z0, z0));
        }
        if (j1 < nv) {
            x1 = verts[3 * j1 + 0]; y1 = verts[3 * j1 + 1]; z1 = verts[3 * j1 + 2];
            w1 = __fadd_rn(__fadd_rn(__fmul_rn(x1, x1), __fmul_rn(y1, y1)),
                           __fmul_rn(z1, z1));
        }
        sv4[2 * p]     = make_float4(x0, x1, y0, y1);
        sv4[2 * p + 1] = make_float4(z0, z1, w0, w1);
    }
    __syncthreads();

    const int pt0 = chunk * PTS_PER_CTA + 2 * tid;
    const int pt1 = pt0 + 1;
    if (pt0 >= n) return;
    const int pt1c = (pt1 < n) ? pt1 : pt0;

    const float px0 = xyz[3 * pt0 + 0], py0 = xyz[3 * pt0 + 1], pz0 = xyz[3 * pt0 + 2];
    const float px1 = xyz[3 * pt1c + 0], py1 = xyz[3 * pt1c + 1], pz1 = xyz[3 * pt1c + 2];

    const float sx0 = __fadd_rn(__fadd_rn(__fmul_rn(px0, px0), __fmul_rn(py0, py0)),
                                __fmul_rn(pz0, pz0));
    const float sx1 = __fadd_rn(__fadd_rn(__fmul_rn(px1, px1), __fmul_rn(py1, py1)),
                                __fmul_rn(pz1, pz1));

    const ull Px0 = f2_pack(px0, px0), Py0 = f2_pack(py0, py0), Pz0 = f2_pack(pz0, pz0);
    const ull Px1 = f2_pack(px1, px1), Py1 = f2_pack(py1, py1), Pz1 = f2_pack(pz1, pz1);
    const ull Sx0 = f2_pack(sx0, sx0), Sx1 = f2_pack(sx1, sx1);
    const ull M2  = f2_pack(-2.0f, -2.0f);

    float best0 = CUDART_INF_F, best1 = CUDART_INF_F;
    int   bg0 = 0, bg1 = 0;

    const ulonglong2* svp = reinterpret_cast<const ulonglong2*>(smem);

    #pragma unroll 2
    for (int g = 0; g < NGROUPS_H; ++g) {
        const ulonglong2* q = svp + (size_t)g * 8;
        float2 a[4], b[4];
        group_d2(q, Px0, Py0, Pz0, Sx0, M2, a);
        group_d2(q, Px1, Py1, Pz1, Sx1, M2, b);

        float g0 = fminf(fminf(fminf(a[0].x, a[0].y), fminf(a[1].x, a[1].y)),
                         fminf(fminf(a[2].x, a[2].y), fminf(a[3].x, a[3].y)));
        float g1 = fminf(fminf(fminf(b[0].x, b[0].y), fminf(b[1].x, b[1].y)),
                         fminf(fminf(b[2].x, b[2].y), fminf(b[3].x, b[3].y)));

        bool c0 = (g0 < best0);      // strict <: first group attaining min wins
        bool c1 = (g1 < best1);
        best0 = c0 ? g0 : best0;  bg0 = c0 ? g : bg0;
        best1 = c1 ? g1 : best1;  bg1 = c1 ? g : bg1;
    }

    // Recover the first index within the winning group (recompute once).
    int bidx0, bidx1;
    {
        float2 a[4];
        group_d2(svp + (size_t)bg0 * 8, Px0, Py0, Pz0, Sx0, M2, a);
        float d[8] = {a[0].x, a[0].y, a[1].x, a[1].y, a[2].x, a[2].y, a[3].x, a[3].y};
        int off = 0;
        #pragma unroll
        for (int u = 7; u >= 0; --u)
            if (d[u] == best0) off = u;
        bidx0 = vbase + bg0 * 8 + off;
    }
    {
        float2 b[4];
        group_d2(svp + (size_t)bg1 * 8, Px1, Py1, Pz1, Sx1, M2, b);
        float d[8] = {b[0].x, b[0].y, b[1].x, b[1].y, b[2].x, b[2].y, b[3].x, b[3].y};
        int off = 0;
        #pragma unroll
        for (int u = 7; u >= 0; --u)
            if (d[u] == best1) off = u;
        bidx1 = vbase + bg1 * 8 + off;
    }

    g_best[half][pt0] = best0;  g_bidx[half][pt0] = bidx0;
    if (pt1 < n) { g_best[half][pt1] = best1;  g_bidx[half][pt1] = bidx1; }
}

// ───────────────────────── Kernel B: finish ─────────────────────────
__global__ void __launch_bounds__(256) finish_kernel(
    const float* __restrict__ xyz,
    const float* __restrict__ rot,
    const float* __restrict__ W,
    const float* __restrict__ bones,
    float* __restrict__ out,
    int n)
{
    __shared__ float sB[24 * 16];
    const int tid = threadIdx.x;
    for (int j = tid; j < 24 * 16; j += blockDim.x) sB[j] = bones[j];
    __syncthreads();

    const int pt = blockIdx.x * blockDim.x + tid;
    if (pt >= n) return;

    // Combine halves: strict < keeps half0 on ties (lower indices scanned first).
    float b0 = g_best[0][pt];
    float b1 = g_best[1][pt];
    int bidx = (b1 < b0) ? g_bidx[1][pt] : g_bidx[0][pt];

    const float px = xyz[3 * pt + 0];
    const float py = xyz[3 * pt + 1];
    const float pz = xyz[3 * pt + 2];

    float T[16];
    #pragma unroll
    for (int k = 0; k < 16; ++k) T[k] = 0.0f;

    const float* wrow = W + (size_t)bidx * 24;
    #pragma unroll
    for (int j = 0; j < 24; ++j) {
        float wj = __ldg(wrow + j);
        #pragma unroll
        for (int k = 0; k < 16; ++k) T[k] = fmaf(wj, sB[j * 16 + k], T[k]);
    }

    // x_bar = T[:3,:] @ [x,1]
    #pragma unroll
    for (int i = 0; i < 3; ++i) {
        float v = T[4 * i + 3];
        v = fmaf(T[4 * i + 0], px, v);
        v = fmaf(T[4 * i + 1], py, v);
        v = fmaf(T[4 * i + 2], pz, v);
        out[3 * pt + i] = v;
    }

    // Quaternion -> rotation matrix
    const float4 q = *reinterpret_cast<const float4*>(rot + 4 * pt);
    float qn = rsqrtf(q.x * q.x + q.y * q.y + q.z * q.z + q.w * q.w);
    float qr = q.x * qn, qx = q.y * qn, qy = q.z * qn, qz = q.w * qn;

    float R[3][3];
    R[0][0] = 1.0f - 2.0f * (qy * qy + qz * qz);
    R[0][1] = 2.0f * (qx * qy - qr * qz);
    R[0][2] = 2.0f * (qx * qz + qr * qy);
    R[1][0] = 2.0f * (qx * qy + qr * qz);
    R[1][1] = 1.0f - 2.0f * (qx * qx + qz * qz);
    R[1][2] = 2.0f * (qy * qz - qr * qx);
    R[2][0] = 2.0f * (qx * qz - qr * qy);
    R[2][1] = 2.0f * (qy * qz + qr * qx);
    R[2][2] = 1.0f - 2.0f * (qx * qx + qy * qy);

    // rotation_bar = T[:3,:3] @ R
    float* out_R = out + (size_t)3 * n;
    #pragma unroll
    for (int i = 0; i < 3; ++i) {
        #pragma unroll
        for (int k = 0; k < 3; ++k) {
            float v = T[4 * i + 0] * R[0][k];
            v = fmaf(T[4 * i + 1], R[1][k], v);
            v = fmaf(T[4 * i + 2], R[2][k], v);
            out_R[9 * pt + 3 * i + k] = v;
        }
    }

    // T_fwd (full 4x4)
    float4* out_T = reinterpret_cast<float4*>(out + (size_t)12 * n) + (size_t)4 * pt;
    #pragma unroll
    for (int k = 0; k < 4; ++k)
        out_T[k] = make_float4(T[4 * k + 0], T[4 * k + 1], T[4 * k + 2], T[4 * k + 3]);
}

extern "C" void kernel_launch(void* const* d_in, const int* in_sizes, int n_in,
                              void* d_out, int out_size)
{
    const float* xyz   = (const float*)d_in[0];
    const float* rot   = (const float*)d_in[1];
    const float* verts = (const float*)d_in[2];
    const float* W     = (const float*)d_in[3];
    const float* bones = (const float*)d_in[4];
    float* out = (float*)d_out;

    const int n  = in_sizes[0] / 3;   // 100000
    const int nv = in_sizes[2] / 3;   // 6890

    const size_t smemA = (size_t)NPAIRS_H * 8 * sizeof(float);   // 55168 B
    cudaFuncSetAttribute(scan_kernel,
                         cudaFuncAttributeMaxDynamicSharedMemorySize, (int)smemA);

    const int chunks = (n + PTS_PER_CTA - 1) / PTS_PER_CTA;      // 143
    scan_kernel<<<chunks * 2, THREADS, smemA>>>(xyz, verts, n, nv);

    const int blocksB = (n + 255) / 256;
    finish_kernel<<<blocksB, 256>>>(xyz, rot, W, bones, out, n);
}